// round 5
// baseline (speedup 1.0000x reference)
#include <cuda_runtime.h>
#include <math.h>
#include <stdint.h>

#define B_ 2
#define S_ 2048
#define D_ 1024
#define H_ 16
#define DK_ 64
#define FF_ 4096
#define NEG_ (-1000000000.0f)

// ---------------- scratch buffers ----------------
__device__ float g_n1[(size_t)B_ * S_ * D_];    // tf32 bits
__device__ float g_q [(size_t)B_ * S_ * D_];    // fp32
__device__ float g_k [(size_t)B_ * S_ * D_];    // fp32
__device__ float g_v [(size_t)B_ * S_ * D_];    // fp32
__device__ float g_o [(size_t)B_ * S_ * D_];    // tf32 bits
__device__ float g_x1[(size_t)B_ * S_ * D_];    // fp32
__device__ float g_n2[(size_t)B_ * S_ * D_];    // tf32 bits
__device__ float g_ff[(size_t)B_ * S_ * FF_];   // tf32 bits
// pre-converted tf32 weights
__device__ uint32_t g_Wqc[(size_t)D_ * D_];
__device__ uint32_t g_Wkc[(size_t)D_ * D_];
__device__ uint32_t g_Wvc[(size_t)D_ * D_];
__device__ uint32_t g_Woc[(size_t)D_ * D_];
__device__ uint32_t g_W1c[(size_t)D_ * FF_];
__device__ uint32_t g_W2c[(size_t)FF_ * D_];

__device__ __forceinline__ uint32_t f2tf32(float f) {
    uint32_t r; asm("cvt.rna.tf32.f32 %0, %1;" : "=r"(r) : "f"(f)); return r;
}

__device__ __forceinline__ void mma_tf32(float c[4], const uint32_t a[4], const uint32_t b[2]) {
    asm volatile(
        "mma.sync.aligned.m16n8k8.row.col.f32.tf32.tf32.f32 "
        "{%0,%1,%2,%3}, {%4,%5,%6,%7}, {%8,%9}, {%0,%1,%2,%3};"
        : "+f"(c[0]), "+f"(c[1]), "+f"(c[2]), "+f"(c[3])
        : "r"(a[0]), "r"(a[1]), "r"(a[2]), "r"(a[3]), "r"(b[0]), "r"(b[1]));
}

// ---------------- weight pre-convert: fp32 -> tf32(RN) bits ----------------
__global__ __launch_bounds__(256) void cvtw_kernel(const float* __restrict__ in,
                                                   uint32_t* __restrict__ out)
{
    const int i = (blockIdx.x * 256 + threadIdx.x) * 4;
    const float4 v = *reinterpret_cast<const float4*>(in + i);
    uint4 u;
    u.x = f2tf32(v.x); u.y = f2tf32(v.y); u.z = f2tf32(v.z); u.w = f2tf32(v.w);
    *reinterpret_cast<uint4*>(out + i) = u;
}

// ================= tf32 tensor-core GEMM, fragment-packed smem =================
// C[M,N] = act(A[M,K] @ W[K,N] + bias) (+ res); A, W already tf32 bits.
#define BM 128
#define BN 128
#define BK 16

__global__ __launch_bounds__(256) void mmagemm_kernel(const uint32_t* __restrict__ A,
                                                      const uint32_t* __restrict__ W,
                                                      const float* __restrict__ bias,
                                                      const float* __restrict__ res,
                                                      float* __restrict__ C,
                                                      int M, int N, int K, int act, int outtf)
{
    __shared__ alignas(128) char Asm[2 * 8192];
    __shared__ alignas(128) char Bsm[2 * 8192];

    const int tid = threadIdx.x;
    const int wid = tid >> 5, lane = tid & 31;
    const int row0 = blockIdx.y * BM;
    const int col0 = blockIdx.x * BN;

    const int m0w = (wid >> 2) * 64;
    const int n0w = (wid & 3) * 32;
    const int g16b = m0w >> 4;
    const int bg8 = n0w >> 3;

    // ---- A loader: thread handles rows (ar, ar+64), cols ac..ac+3
    const int ar = tid >> 2;
    const int ac = (tid & 3) << 2;
    const int lga = ar & 7;
    const int swa = (lga >> 1) & 3;
    const int abase = ((ac >> 3) * 8 + (ar >> 4)) * 512 +
                      ((((ac >> 2) & 1) * 2) + ((ar >> 3) & 1)) * 4;
    int aoff[4];
#pragma unroll
    for (int j = 0; j < 4; j++) aoff[j] = abase + (((lga * 4 + j) ^ swa) << 4);

    // ---- B loader: thread handles (k=bk and bk+8) x (n = bnq..bnq+3)
    const int bnq = (tid & 31) << 2;   // n0: 0,4,...,124
    const int bk  = tid >> 5;          // 0..7
    const int bg8l = bnq >> 3;
    const int bswz = bg8l & 3;
    const int blt = bk & 3;
    const int bword = (bk >> 2) << 2;  // byte offset of word within slot
    int boffs[2][4];
#pragma unroll
    for (int kb = 0; kb < 2; kb++)
#pragma unroll
        for (int j = 0; j < 4; j++) {
            const int nn7 = (bnq & 7) + j;
            boffs[kb][j] = ((kb * 16 + bg8l) << 8) + (((nn7 * 4 + blt) ^ bswz) << 3) + bword;
        }

    const int aslot = ((lane ^ ((lane >> 3) & 3)) << 4);

    float acc[4][4][4];
#pragma unroll
    for (int mi = 0; mi < 4; mi++)
#pragma unroll
        for (int ni = 0; ni < 4; ni++)
#pragma unroll
            for (int r = 0; r < 4; r++) acc[mi][ni][r] = 0.f;

    const int NC = K / BK;

    // prologue: chunk 0 -> buffer 0
    {
        const uint4 av0 = *reinterpret_cast<const uint4*>(A + (size_t)(row0 + ar) * K + ac);
        const uint4 av1 = *reinterpret_cast<const uint4*>(A + (size_t)(row0 + 64 + ar) * K + ac);
        const uint32_t a0[4] = {av0.x, av0.y, av0.z, av0.w};
        const uint32_t a1[4] = {av1.x, av1.y, av1.z, av1.w};
#pragma unroll
        for (int j = 0; j < 4; j++) {
            *reinterpret_cast<uint32_t*>(Asm + aoff[j]) = a0[j];
            *reinterpret_cast<uint32_t*>(Asm + aoff[j] + 2048) = a1[j];
        }
        const uint4 bv0 = *reinterpret_cast<const uint4*>(W + (size_t)bk * N + col0 + bnq);
        const uint4 bv1 = *reinterpret_cast<const uint4*>(W + (size_t)(bk + 8) * N + col0 + bnq);
        const uint32_t b0[4] = {bv0.x, bv0.y, bv0.z, bv0.w};
        const uint32_t b1[4] = {bv1.x, bv1.y, bv1.z, bv1.w};
#pragma unroll
        for (int j = 0; j < 4; j++) {
            *reinterpret_cast<uint32_t*>(Bsm + boffs[0][j]) = b0[j];
            *reinterpret_cast<uint32_t*>(Bsm + boffs[1][j]) = b1[j];
        }
    }
    __syncthreads();

    for (int c = 0; c < NC; c++) {
        const int buf = c & 1;
        const char* Ab = Asm + buf * 8192;
        const char* Bb = Bsm + buf * 8192;

        uint4 av0, av1, bv0, bv1;
        if (c + 1 < NC) {
            const int k0 = (c + 1) * BK;
            av0 = *reinterpret_cast<const uint4*>(A + (size_t)(row0 + ar) * K + k0 + ac);
            av1 = *reinterpret_cast<const uint4*>(A + (size_t)(row0 + 64 + ar) * K + k0 + ac);
            bv0 = *reinterpret_cast<const uint4*>(W + (size_t)(k0 + bk) * N + col0 + bnq);
            bv1 = *reinterpret_cast<const uint4*>(W + (size_t)(k0 + bk + 8) * N + col0 + bnq);
        }

#pragma unroll
        for (int kb = 0; kb < 2; kb++) {
            const char* Abk = Ab + (kb << 12);
            const char* Bbk = Bb + (kb << 12);
            uint4 afr[4];
            uint2 bfr[4];
#pragma unroll
            for (int mi = 0; mi < 4; mi++)
                afr[mi] = *reinterpret_cast<const uint4*>(Abk + ((g16b + mi) << 9) + aslot);
#pragma unroll
            for (int ni = 0; ni < 4; ni++) {
                const int g8 = bg8 + ni;
                bfr[ni] = *reinterpret_cast<const uint2*>(Bbk + (g8 << 8) + ((lane ^ (g8 & 3)) << 3));
            }
#pragma unroll
            for (int mi = 0; mi < 4; mi++)
#pragma unroll
                for (int ni = 0; ni < 4; ni++)
                    mma_tf32(acc[mi][ni],
                             reinterpret_cast<const uint32_t*>(&afr[mi]),
                             reinterpret_cast<const uint32_t*>(&bfr[ni]));
        }

        if (c + 1 < NC) {
            char* An = Asm + (buf ^ 1) * 8192;
            char* Bn = Bsm + (buf ^ 1) * 8192;
            const uint32_t a0[4] = {av0.x, av0.y, av0.z, av0.w};
            const uint32_t a1[4] = {av1.x, av1.y, av1.z, av1.w};
            const uint32_t b0[4] = {bv0.x, bv0.y, bv0.z, bv0.w};
            const uint32_t b1[4] = {bv1.x, bv1.y, bv1.z, bv1.w};
#pragma unroll
            for (int j = 0; j < 4; j++) {
                *reinterpret_cast<uint32_t*>(An + aoff[j]) = a0[j];
                *reinterpret_cast<uint32_t*>(An + aoff[j] + 2048) = a1[j];
                *reinterpret_cast<uint32_t*>(Bn + boffs[0][j]) = b0[j];
                *reinterpret_cast<uint32_t*>(Bn + boffs[1][j]) = b1[j];
            }
            __syncthreads();
        }
    }

    // epilogue
    const int lg = lane >> 2, lt = lane & 3;
#pragma unroll
    for (int mi = 0; mi < 4; mi++) {
#pragma unroll
        for (int half = 0; half < 2; half++) {
            const int r = row0 + m0w + mi * 16 + lg + half * 8;
#pragma unroll
            for (int ni = 0; ni < 4; ni++) {
                const int cc = col0 + n0w + ni * 8 + lt * 2;
                float2 o;
                o.x = acc[mi][ni][half * 2 + 0] + bias[cc];
                o.y = acc[mi][ni][half * 2 + 1] + bias[cc + 1];
                if (act == 1) {
                    o.x = 0.5f * o.x * (1.0f + erff(o.x * 0.70710678118654752f));
                    o.y = 0.5f * o.y * (1.0f + erff(o.y * 0.70710678118654752f));
                }
                if (res) {
                    const float2 rv = *reinterpret_cast<const float2*>(res + (size_t)r * N + cc);
                    o.x += rv.x; o.y += rv.y;
                }
                if (outtf) {
                    o.x = __uint_as_float(f2tf32(o.x));
                    o.y = __uint_as_float(f2tf32(o.y));
                }
                *reinterpret_cast<float2*>(C + (size_t)r * N + cc) = o;
            }
        }
    }
}

// ---------------- LayerNorm (always emits tf32 bits; feeds GEMMs only) -------
__global__ __launch_bounds__(256) void ln_kernel(const float* __restrict__ x,
                                                 const float* __restrict__ g,
                                                 const float* __restrict__ b,
                                                 float* __restrict__ out)
{
    const int row = blockIdx.x;
    const float* xr = x + (size_t)row * D_;
    float* outr = out + (size_t)row * D_;
    const int tid = threadIdx.x;

    float4 v = reinterpret_cast<const float4*>(xr)[tid];
    float s = v.x + v.y + v.z + v.w;
    float ss = v.x * v.x + v.y * v.y + v.z * v.z + v.w * v.w;

    __shared__ float sh_s[8], sh_ss[8];
    for (int off = 16; off; off >>= 1) {
        s  += __shfl_xor_sync(0xffffffffu, s, off);
        ss += __shfl_xor_sync(0xffffffffu, ss, off);
    }
    const int wid = tid >> 5, lane = tid & 31;
    if (lane == 0) { sh_s[wid] = s; sh_ss[wid] = ss; }
    __syncthreads();
    if (wid == 0) {
        s  = (lane < 8) ? sh_s[lane]  : 0.f;
        ss = (lane < 8) ? sh_ss[lane] : 0.f;
        for (int off = 4; off; off >>= 1) {
            s  += __shfl_xor_sync(0xffffffffu, s, off);
            ss += __shfl_xor_sync(0xffffffffu, ss, off);
        }
        if (lane == 0) { sh_s[0] = s; sh_ss[0] = ss; }
    }
    __syncthreads();
    const float mu = sh_s[0] * (1.0f / D_);
    const float var = sh_ss[0] * (1.0f / D_) - mu * mu;
    const float rstd = rsqrtf(var + 1e-5f);

    float4 gv = reinterpret_cast<const float4*>(g)[tid];
    float4 bv = reinterpret_cast<const float4*>(b)[tid];
    uint4 o;
    o.x = f2tf32((v.x - mu) * rstd * gv.x + bv.x);
    o.y = f2tf32((v.y - mu) * rstd * gv.y + bv.y);
    o.z = f2tf32((v.z - mu) * rstd * gv.z + bv.z);
    o.w = f2tf32((v.w - mu) * rstd * gv.w + bv.w);
    reinterpret_cast<uint4*>(outr)[tid] = o;
}

// ================= sparse attention (smem K/V tile, lane-parallel keys) ======
// Emits tf32 bits (feeds Wo GEMM only).
#define QB 64
#define KW 192
#define KP 65
#define ATTN_SMEM (2 * KW * KP * 4)

__global__ __launch_bounds__(256) void attn2_kernel(const float* __restrict__ Q,
                                                    const float* __restrict__ K,
                                                    const float* __restrict__ V,
                                                    const int* __restrict__ mask,
                                                    float* __restrict__ O)
{
    extern __shared__ float smattn[];
    float* Ks = smattn;
    float* Vs = smattn + KW * KP;

    const int qb0 = blockIdx.x * QB;
    const int h = blockIdx.y;
    const int b = blockIdx.z;
    const int tid = threadIdx.x;
    const int warp = tid >> 5, lane = tid & 31;
    const int base_row = qb0 - 128;

    for (int idx = tid; idx < KW * 64; idx += 256) {
        const int r = idx >> 6, d = idx & 63;
        const int j = base_row + r;
        if (j >= 0) {
            const size_t g = ((size_t)(b * S_ + j)) * D_ + h * 64 + d;
            Ks[r * KP + d] = K[g];
            Vs[r * KP + d] = V[g];
        }
    }
    __syncthreads();

#pragma unroll 1
    for (int qi = 0; qi < 8; qi++) {
        const int i = qb0 + warp * 8 + qi;
        const float* qrow = Q + ((size_t)(b * S_ + i)) * D_ + h * 64;
        float rq[64];
#pragma unroll
        for (int d = 0; d < 64; d++) rq[d] = __ldg(qrow + d);
        const int* mrow = mask + (size_t)i * S_;

        float m = -INFINITY, l = 0.f, acc0 = 0.f, acc1 = 0.f;

        // strided keys: lane l handles j = i - 256 - 128*l
        {
            const int j = i - 256 - 128 * lane;
            float s = -INFINITY;
            if (j >= 0) {
                const float* kr = K + ((size_t)(b * S_ + j)) * D_ + h * 64;
                float dv = 0.f;
#pragma unroll
                for (int d = 0; d < 64; d++) dv = fmaf(rq[d], __ldg(kr + d), dv);
                s = dv * 0.125f;
                if (mrow[j] == 0) s = NEG_;
            }
            float bm = s;
            for (int off = 16; off; off >>= 1)
                bm = fmaxf(bm, __shfl_xor_sync(0xffffffffu, bm, off));
            if (bm > -1e37f) {
                const float nm = fmaxf(m, bm);
                const float sc = __expf(m - nm);
                const float p = __expf(s - nm);
                float bs = p;
                for (int off = 16; off; off >>= 1)
                    bs += __shfl_xor_sync(0xffffffffu, bs, off);
                l = l * sc + bs;
                acc0 *= sc; acc1 *= sc;
                m = nm;
                const int cnt = (i - 256) / 128 + 1;
                for (int l2 = 0; l2 < cnt; l2++) {
                    const float pv = __shfl_sync(0xffffffffu, p, l2);
                    const int j2 = i - 256 - 128 * l2;
                    const float* vr = V + ((size_t)(b * S_ + j2)) * D_ + h * 64;
                    acc0 = fmaf(pv, __ldg(vr + lane), acc0);
                    acc1 = fmaf(pv, __ldg(vr + lane + 32), acc1);
                }
            }
        }

        // local window [i-128, i]: 5 batches of 32
#pragma unroll 1
        for (int t = 0; t < 5; t++) {
            const int jb = i - 128 + t * 32;
            const int j = jb + lane;
            float s = -INFINITY;
            if (j >= 0 && j <= i) {
                const float* kr = Ks + (j - base_row) * KP;
                float dv = 0.f;
#pragma unroll
                for (int d = 0; d < 64; d++) dv = fmaf(rq[d], kr[d], dv);
                s = dv * 0.125f;
                if (mrow[j] == 0) s = NEG_;
            }
            float bm = s;
            for (int off = 16; off; off >>= 1)
                bm = fmaxf(bm, __shfl_xor_sync(0xffffffffu, bm, off));
            if (bm > -1e37f) {
                const float nm = fmaxf(m, bm);
                const float sc = __expf(m - nm);
                const float p = __expf(s - nm);
                float bs = p;
                for (int off = 16; off; off >>= 1)
                    bs += __shfl_xor_sync(0xffffffffu, bs, off);
                l = l * sc + bs;
                acc0 *= sc; acc1 *= sc;
                m = nm;
                const int l2lo = (jb < 0) ? -jb : 0;
                const int l2hi = (i - jb < 31) ? (i - jb) : 31;
                for (int l2 = l2lo; l2 <= l2hi; l2++) {
                    const float pv = __shfl_sync(0xffffffffu, p, l2);
                    const float* vr = Vs + (jb + l2 - base_row) * KP;
                    acc0 = fmaf(pv, vr[lane], acc0);
                    acc1 = fmaf(pv, vr[lane + 32], acc1);
                }
            }
        }

        const float inv = 1.0f / l;
        float* orow = O + ((size_t)(b * S_ + i)) * D_ + h * 64;
        orow[lane]      = __uint_as_float(f2tf32(acc0 * inv));
        orow[lane + 32] = __uint_as_float(f2tf32(acc1 * inv));
    }
}

// ---------------- host launcher ----------------
extern "C" void kernel_launch(void* const* d_in, const int* in_sizes, int n_in,
                              void* d_out, int out_size)
{
    (void)in_sizes; (void)n_in; (void)out_size;
    const float* x    = (const float*)d_in[0];
    const int*   mask = (const int*)  d_in[1];
    const float* Wq = (const float*)d_in[2];  const float* bq = (const float*)d_in[3];
    const float* Wk = (const float*)d_in[4];  const float* bk = (const float*)d_in[5];
    const float* Wv = (const float*)d_in[6];  const float* bv = (const float*)d_in[7];
    const float* Wo = (const float*)d_in[8];  const float* bo = (const float*)d_in[9];
    const float* W1 = (const float*)d_in[10]; const float* bf1 = (const float*)d_in[11];
    const float* W2 = (const float*)d_in[12]; const float* bf2 = (const float*)d_in[13];
    const float* g1 = (const float*)d_in[14]; const float* bl1 = (const float*)d_in[15];
    const float* g2 = (const float*)d_in[16]; const float* bl2 = (const float*)d_in[17];
    float* out = (float*)d_out;

    float *n1, *q, *k, *v, *o, *x1, *n2, *ff;
    uint32_t *Wqc, *Wkc, *Wvc, *Woc, *W1c, *W2c;
    cudaGetSymbolAddress((void**)&n1, g_n1);
    cudaGetSymbolAddress((void**)&q,  g_q);
    cudaGetSymbolAddress((void**)&k,  g_k);
    cudaGetSymbolAddress((void**)&v,  g_v);
    cudaGetSymbolAddress((void**)&o,  g_o);
    cudaGetSymbolAddress((void**)&x1, g_x1);
    cudaGetSymbolAddress((void**)&n2, g_n2);
    cudaGetSymbolAddress((void**)&ff, g_ff);
    cudaGetSymbolAddress((void**)&Wqc, g_Wqc);
    cudaGetSymbolAddress((void**)&Wkc, g_Wkc);
    cudaGetSymbolAddress((void**)&Wvc, g_Wvc);
    cudaGetSymbolAddress((void**)&Woc, g_Woc);
    cudaGetSymbolAddress((void**)&W1c, g_W1c);
    cudaGetSymbolAddress((void**)&W2c, g_W2c);

    cudaFuncSetAttribute(attn2_kernel, cudaFuncAttributeMaxDynamicSharedMemorySize, ATTN_SMEM);

    const int M = B_ * S_;  // 4096

    // 0) weight pre-convert to tf32 bits
    cvtw_kernel<<<(D_ * D_) / 1024, 256>>>(Wq, Wqc);
    cvtw_kernel<<<(D_ * D_) / 1024, 256>>>(Wk, Wkc);
    cvtw_kernel<<<(D_ * D_) / 1024, 256>>>(Wv, Wvc);
    cvtw_kernel<<<(D_ * D_) / 1024, 256>>>(Wo, Woc);
    cvtw_kernel<<<(D_ * FF_) / 1024, 256>>>(W1, W1c);
    cvtw_kernel<<<(FF_ * D_) / 1024, 256>>>(W2, W2c);

    // 1) LN1 -> n1 (tf32)
    ln_kernel<<<M, 256>>>(x, g1, bl1, n1);

    // 2) Q, K, V projections (fp32 out)
    {
        dim3 grid(D_ / BN, M / BM);
        mmagemm_kernel<<<grid, 256>>>((const uint32_t*)n1, Wqc, bq, nullptr, q, M, D_, D_, 0, 0);
        mmagemm_kernel<<<grid, 256>>>((const uint32_t*)n1, Wkc, bk, nullptr, k, M, D_, D_, 0, 0);
        mmagemm_kernel<<<grid, 256>>>((const uint32_t*)n1, Wvc, bv, nullptr, v, M, D_, D_, 0, 0);
    }

    // 3) sparse attention -> o (tf32)
    {
        dim3 grid(S_ / QB, H_, B_);
        attn2_kernel<<<grid, 256, ATTN_SMEM>>>(q, k, v, mask, o);
    }

    // 4) output projection + residual -> x1 (fp32)
    {
        dim3 grid(D_ / BN, M / BM);
        mmagemm_kernel<<<grid, 256>>>((const uint32_t*)o, Woc, bo, x, x1, M, D_, D_, 0, 0);
    }

    // 5) LN2 -> n2 (tf32)
    ln_kernel<<<M, 256>>>(x1, g2, bl2, n2);

    // 6) FFN up + GELU -> ff (tf32)
    {
        dim3 grid(FF_ / BN, M / BM);
        mmagemm_kernel<<<grid, 256>>>((const uint32_t*)n2, W1c, bf1, nullptr, ff, M, FF_, D_, 1, 1);
    }

    // 7) FFN down + residual -> out (fp32)
    {
        dim3 grid(D_ / BN, M / BM);
        mmagemm_kernel<<<grid, 256>>>((const uint32_t*)ff, W2c, bf2, x1, out, M, D_, FF_, 0, 0);
    }
}

// round 6
// speedup vs baseline: 1.1563x; 1.1563x over previous
#include <cuda_runtime.h>
#include <math.h>
#include <stdint.h>

#define B_ 2
#define S_ 2048
#define D_ 1024
#define H_ 16
#define DK_ 64
#define FF_ 4096
#define NEG_ (-1000000000.0f)

// ---------------- scratch buffers ----------------
__device__ float g_n1[(size_t)B_ * S_ * D_];    // tf32 bits
__device__ float g_q [(size_t)B_ * S_ * D_];    // fp32
__device__ float g_k [(size_t)B_ * S_ * D_];    // fp32
__device__ float g_v [(size_t)B_ * S_ * D_];    // fp32
__device__ float g_o [(size_t)B_ * S_ * D_];    // tf32 bits
__device__ float g_x1[(size_t)B_ * S_ * D_];    // fp32
__device__ float g_n2[(size_t)B_ * S_ * D_];    // tf32 bits
__device__ float g_ff[(size_t)B_ * S_ * FF_];   // tf32 bits
// pre-converted tf32 weights
__device__ uint32_t g_Wqc[(size_t)D_ * D_];
__device__ uint32_t g_Wkc[(size_t)D_ * D_];
__device__ uint32_t g_Wvc[(size_t)D_ * D_];
__device__ uint32_t g_Woc[(size_t)D_ * D_];
__device__ uint32_t g_W1c[(size_t)D_ * FF_];
__device__ uint32_t g_W2c[(size_t)FF_ * D_];

__device__ __forceinline__ uint32_t f2tf32(float f) {
    uint32_t r; asm("cvt.rna.tf32.f32 %0, %1;" : "=r"(r) : "f"(f)); return r;
}

__device__ __forceinline__ void mma_tf32(float c[4], const uint32_t a[4], const uint32_t b[2]) {
    asm volatile(
        "mma.sync.aligned.m16n8k8.row.col.f32.tf32.tf32.f32 "
        "{%0,%1,%2,%3}, {%4,%5,%6,%7}, {%8,%9}, {%0,%1,%2,%3};"
        : "+f"(c[0]), "+f"(c[1]), "+f"(c[2]), "+f"(c[3])
        : "r"(a[0]), "r"(a[1]), "r"(a[2]), "r"(a[3]), "r"(b[0]), "r"(b[1]));
}

// ---------------- weight pre-convert: fp32 -> tf32(RN) bits ----------------
__global__ __launch_bounds__(256) void cvtw_kernel(const float* __restrict__ in,
                                                   uint32_t* __restrict__ out)
{
    const int i = (blockIdx.x * 256 + threadIdx.x) * 4;
    const float4 v = *reinterpret_cast<const float4*>(in + i);
    uint4 u;
    u.x = f2tf32(v.x); u.y = f2tf32(v.y); u.z = f2tf32(v.z); u.w = f2tf32(v.w);
    *reinterpret_cast<uint4*>(out + i) = u;
}

// ================= tf32 tensor-core GEMM (R4 structure, pre-converted data) ===
#define BM 128
#define BN 128
#define BK 16

__global__ __launch_bounds__(256) void mmagemm_kernel(const uint32_t* __restrict__ A,
                                                      const uint32_t* __restrict__ W,
                                                      const float* __restrict__ bias,
                                                      const float* __restrict__ res,
                                                      float* __restrict__ C,
                                                      int M, int N, int K, int act, int outtf)
{
    __shared__ alignas(128) char Asm[2 * 8192];
    __shared__ alignas(128) char Bsm[2 * 8192];

    const int tid = threadIdx.x;
    const int wid = tid >> 5, lane = tid & 31;
    const int row0 = blockIdx.y * BM;
    const int col0 = blockIdx.x * BN;

    const int m0w = (wid >> 2) * 64;      // warp m origin (0 or 64)
    const int n0w = (wid & 3) * 32;       // warp n origin
    const int g16b = m0w >> 4;            // 0 or 4
    const int bg8 = n0w >> 3;             // 0,4,8,12

    // ---- A loader indices: thread handles rows (ar, ar+64), cols ac..ac+3
    const int ar = tid >> 2;
    const int ac = (tid & 3) << 2;
    const int lga = ar & 7;
    const int swa = (lga >> 1) & 3;
    const int abase = ((ac >> 3) * 8 + (ar >> 4)) * 512 +
                      ((((ac >> 2) & 1) * 2) + ((ar >> 3) & 1)) * 4;
    int aoff[4];
#pragma unroll
    for (int j = 0; j < 4; j++) aoff[j] = abase + (((lga * 4 + j) ^ swa) << 4);

    // ---- B loader indices: thread handles n in {nn, nn+64}, k rows kq+{0,4,8,12}
    const int kq = tid >> 6;              // 0..3
    const int nn = tid & 63;
    int boff[2][2];                        // [t (n half)][kb]
#pragma unroll
    for (int t = 0; t < 2; t++) {
        const int nv = nn + t * 64;
        const int g8 = nv >> 3;
        const int slot = (((nv & 7) * 4 + kq) ^ (g8 & 3));
#pragma unroll
        for (int kb = 0; kb < 2; kb++)
            boff[t][kb] = ((kb * 16 + g8) << 8) + slot * 8;
    }

    // ---- fragment load offsets
    const int aslot = ((lane ^ ((lane >> 3) & 3)) << 4);

    float acc[4][4][4];
#pragma unroll
    for (int mi = 0; mi < 4; mi++)
#pragma unroll
        for (int ni = 0; ni < 4; ni++)
#pragma unroll
            for (int r = 0; r < 4; r++) acc[mi][ni][r] = 0.f;

    const int NC = K / BK;

    // prologue: chunk 0 -> buffer 0
    {
        const uint4 av0 = *reinterpret_cast<const uint4*>(A + (size_t)(row0 + ar) * K + ac);
        const uint4 av1 = *reinterpret_cast<const uint4*>(A + (size_t)(row0 + 64 + ar) * K + ac);
        const uint32_t a0[4] = {av0.x, av0.y, av0.z, av0.w};
        const uint32_t a1[4] = {av1.x, av1.y, av1.z, av1.w};
#pragma unroll
        for (int j = 0; j < 4; j++) {
            *reinterpret_cast<uint32_t*>(Asm + aoff[j]) = a0[j];
            *reinterpret_cast<uint32_t*>(Asm + aoff[j] + 2048) = a1[j];
        }
        uint32_t wreg[2][4];
#pragma unroll
        for (int t = 0; t < 2; t++)
#pragma unroll
            for (int s = 0; s < 4; s++)
                wreg[t][s] = W[(size_t)(kq + s * 4) * N + col0 + nn + t * 64];
#pragma unroll
        for (int t = 0; t < 2; t++)
#pragma unroll
            for (int kb = 0; kb < 2; kb++) {
                uint2 u = {wreg[t][kb * 2 + 0], wreg[t][kb * 2 + 1]};
                *reinterpret_cast<uint2*>(Bsm + boff[t][kb]) = u;
            }
    }
    __syncthreads();

    for (int c = 0; c < NC; c++) {
        const int buf = c & 1;
        const char* Ab = Asm + buf * 8192;
        const char* Bb = Bsm + buf * 8192;

        uint4 av0, av1;
        uint32_t wreg[2][4];
        if (c + 1 < NC) {
            const int k0 = (c + 1) * BK;
            av0 = *reinterpret_cast<const uint4*>(A + (size_t)(row0 + ar) * K + k0 + ac);
            av1 = *reinterpret_cast<const uint4*>(A + (size_t)(row0 + 64 + ar) * K + k0 + ac);
#pragma unroll
            for (int t = 0; t < 2; t++)
#pragma unroll
                for (int s = 0; s < 4; s++)
                    wreg[t][s] = W[(size_t)(k0 + kq + s * 4) * N + col0 + nn + t * 64];
        }

#pragma unroll
        for (int kb = 0; kb < 2; kb++) {
            const char* Abk = Ab + (kb << 12);
            const char* Bbk = Bb + (kb << 12);
            uint4 afr[4];
            uint2 bfr[4];
#pragma unroll
            for (int mi = 0; mi < 4; mi++)
                afr[mi] = *reinterpret_cast<const uint4*>(Abk + ((g16b + mi) << 9) + aslot);
#pragma unroll
            for (int ni = 0; ni < 4; ni++) {
                const int g8 = bg8 + ni;
                bfr[ni] = *reinterpret_cast<const uint2*>(Bbk + (g8 << 8) + ((lane ^ (g8 & 3)) << 3));
            }
#pragma unroll
            for (int mi = 0; mi < 4; mi++)
#pragma unroll
                for (int ni = 0; ni < 4; ni++)
                    mma_tf32(acc[mi][ni],
                             reinterpret_cast<const uint32_t*>(&afr[mi]),
                             reinterpret_cast<const uint32_t*>(&bfr[ni]));
        }

        if (c + 1 < NC) {
            __syncthreads();
            char* An = Asm + (buf ^ 1) * 8192;
            char* Bn = Bsm + (buf ^ 1) * 8192;
            const uint32_t a0[4] = {av0.x, av0.y, av0.z, av0.w};
            const uint32_t a1[4] = {av1.x, av1.y, av1.z, av1.w};
#pragma unroll
            for (int j = 0; j < 4; j++) {
                *reinterpret_cast<uint32_t*>(An + aoff[j]) = a0[j];
                *reinterpret_cast<uint32_t*>(An + aoff[j] + 2048) = a1[j];
            }
#pragma unroll
            for (int t = 0; t < 2; t++)
#pragma unroll
                for (int kb = 0; kb < 2; kb++) {
                    uint2 u = {wreg[t][kb * 2 + 0], wreg[t][kb * 2 + 1]};
                    *reinterpret_cast<uint2*>(Bn + boff[t][kb]) = u;
                }
            __syncthreads();
        }
    }

    // epilogue
    const int lg = lane >> 2, lt = lane & 3;
#pragma unroll
    for (int mi = 0; mi < 4; mi++) {
#pragma unroll
        for (int half = 0; half < 2; half++) {
            const int r = row0 + m0w + mi * 16 + lg + half * 8;
#pragma unroll
            for (int ni = 0; ni < 4; ni++) {
                const int cc = col0 + n0w + ni * 8 + lt * 2;
                float2 o;
                o.x = acc[mi][ni][half * 2 + 0] + bias[cc];
                o.y = acc[mi][ni][half * 2 + 1] + bias[cc + 1];
                if (act == 1) {
                    o.x = 0.5f * o.x * (1.0f + erff(o.x * 0.70710678118654752f));
                    o.y = 0.5f * o.y * (1.0f + erff(o.y * 0.70710678118654752f));
                }
                if (res) {
                    const float2 rv = *reinterpret_cast<const float2*>(res + (size_t)r * N + cc);
                    o.x += rv.x; o.y += rv.y;
                }
                if (outtf) {
                    o.x = __uint_as_float(f2tf32(o.x));
                    o.y = __uint_as_float(f2tf32(o.y));
                }
                *reinterpret_cast<float2*>(C + (size_t)r * N + cc) = o;
            }
        }
    }
}

// ---------------- LayerNorm (emits tf32 bits; feeds GEMMs only) -------------
__global__ __launch_bounds__(256) void ln_kernel(const float* __restrict__ x,
                                                 const float* __restrict__ g,
                                                 const float* __restrict__ b,
                                                 float* __restrict__ out)
{
    const int row = blockIdx.x;
    const float* xr = x + (size_t)row * D_;
    float* outr = out + (size_t)row * D_;
    const int tid = threadIdx.x;

    float4 v = reinterpret_cast<const float4*>(xr)[tid];
    float s = v.x + v.y + v.z + v.w;
    float ss = v.x * v.x + v.y * v.y + v.z * v.z + v.w * v.w;

    __shared__ float sh_s[8], sh_ss[8];
    for (int off = 16; off; off >>= 1) {
        s  += __shfl_xor_sync(0xffffffffu, s, off);
        ss += __shfl_xor_sync(0xffffffffu, ss, off);
    }
    const int wid = tid >> 5, lane = tid & 31;
    if (lane == 0) { sh_s[wid] = s; sh_ss[wid] = ss; }
    __syncthreads();
    if (wid == 0) {
        s  = (lane < 8) ? sh_s[lane]  : 0.f;
        ss = (lane < 8) ? sh_ss[lane] : 0.f;
        for (int off = 4; off; off >>= 1) {
            s  += __shfl_xor_sync(0xffffffffu, s, off);
            ss += __shfl_xor_sync(0xffffffffu, ss, off);
        }
        if (lane == 0) { sh_s[0] = s; sh_ss[0] = ss; }
    }
    __syncthreads();
    const float mu = sh_s[0] * (1.0f / D_);
    const float var = sh_ss[0] * (1.0f / D_) - mu * mu;
    const float rstd = rsqrtf(var + 1e-5f);

    float4 gv = reinterpret_cast<const float4*>(g)[tid];
    float4 bv = reinterpret_cast<const float4*>(b)[tid];
    uint4 o;
    o.x = f2tf32((v.x - mu) * rstd * gv.x + bv.x);
    o.y = f2tf32((v.y - mu) * rstd * gv.y + bv.y);
    o.z = f2tf32((v.z - mu) * rstd * gv.z + bv.z);
    o.w = f2tf32((v.w - mu) * rstd * gv.w + bv.w);
    reinterpret_cast<uint4*>(outr)[tid] = o;
}

// ================= sparse attention (smem K/V tile, lane-parallel keys) ======
#define QB 64
#define KW 192
#define KP 65
#define ATTN_SMEM (2 * KW * KP * 4)

__global__ __launch_bounds__(256) void attn2_kernel(const float* __restrict__ Q,
                                                    const float* __restrict__ K,
                                                    const float* __restrict__ V,
                                                    const int* __restrict__ mask,
                                                    float* __restrict__ O)
{
    extern __shared__ float smattn[];
    float* Ks = smattn;
    float* Vs = smattn + KW * KP;

    const int qb0 = blockIdx.x * QB;
    const int h = blockIdx.y;
    const int b = blockIdx.z;
    const int tid = threadIdx.x;
    const int warp = tid >> 5, lane = tid & 31;
    const int base_row = qb0 - 128;

    for (int idx = tid; idx < KW * 64; idx += 256) {
        const int r = idx >> 6, d = idx & 63;
        const int j = base_row + r;
        if (j >= 0) {
            const size_t g = ((size_t)(b * S_ + j)) * D_ + h * 64 + d;
            Ks[r * KP + d] = K[g];
            Vs[r * KP + d] = V[g];
        }
    }
    __syncthreads();

#pragma unroll 1
    for (int qi = 0; qi < 8; qi++) {
        const int i = qb0 + warp * 8 + qi;
        const float* qrow = Q + ((size_t)(b * S_ + i)) * D_ + h * 64;
        float rq[64];
#pragma unroll
        for (int d = 0; d < 64; d++) rq[d] = __ldg(qrow + d);
        const int* mrow = mask + (size_t)i * S_;

        float m = -INFINITY, l = 0.f, acc0 = 0.f, acc1 = 0.f;

        // strided keys: lane l handles j = i - 256 - 128*l
        {
            const int j = i - 256 - 128 * lane;
            float s = -INFINITY;
            if (j >= 0) {
                const float* kr = K + ((size_t)(b * S_ + j)) * D_ + h * 64;
                float dv = 0.f;
#pragma unroll
                for (int d = 0; d < 64; d++) dv = fmaf(rq[d], __ldg(kr + d), dv);
                s = dv * 0.125f;
                if (mrow[j] == 0) s = NEG_;
            }
            float bm = s;
            for (int off = 16; off; off >>= 1)
                bm = fmaxf(bm, __shfl_xor_sync(0xffffffffu, bm, off));
            if (bm > -1e37f) {
                const float nm = fmaxf(m, bm);
                const float sc = __expf(m - nm);
                const float p = __expf(s - nm);
                float bs = p;
                for (int off = 16; off; off >>= 1)
                    bs += __shfl_xor_sync(0xffffffffu, bs, off);
                l = l * sc + bs;
                acc0 *= sc; acc1 *= sc;
                m = nm;
                const int cnt = (i - 256) / 128 + 1;
                for (int l2 = 0; l2 < cnt; l2++) {
                    const float pv = __shfl_sync(0xffffffffu, p, l2);
                    const int j2 = i - 256 - 128 * l2;
                    const float* vr = V + ((size_t)(b * S_ + j2)) * D_ + h * 64;
                    acc0 = fmaf(pv, __ldg(vr + lane), acc0);
                    acc1 = fmaf(pv, __ldg(vr + lane + 32), acc1);
                }
            }
        }

        // local window [i-128, i]: 5 batches of 32
#pragma unroll 1
        for (int t = 0; t < 5; t++) {
            const int jb = i - 128 + t * 32;
            const int j = jb + lane;
            float s = -INFINITY;
            if (j >= 0 && j <= i) {
                const float* kr = Ks + (j - base_row) * KP;
                float dv = 0.f;
#pragma unroll
                for (int d = 0; d < 64; d++) dv = fmaf(rq[d], kr[d], dv);
                s = dv * 0.125f;
                if (mrow[j] == 0) s = NEG_;
            }
            float bm = s;
            for (int off = 16; off; off >>= 1)
                bm = fmaxf(bm, __shfl_xor_sync(0xffffffffu, bm, off));
            if (bm > -1e37f) {
                const float nm = fmaxf(m, bm);
                const float sc = __expf(m - nm);
                const float p = __expf(s - nm);
                float bs = p;
                for (int off = 16; off; off >>= 1)
                    bs += __shfl_xor_sync(0xffffffffu, bs, off);
                l = l * sc + bs;
                acc0 *= sc; acc1 *= sc;
                m = nm;
                const int l2lo = (jb < 0) ? -jb : 0;
                const int l2hi = (i - jb < 31) ? (i - jb) : 31;
                for (int l2 = l2lo; l2 <= l2hi; l2++) {
                    const float pv = __shfl_sync(0xffffffffu, p, l2);
                    const float* vr = Vs + (jb + l2 - base_row) * KP;
                    acc0 = fmaf(pv, vr[lane], acc0);
                    acc1 = fmaf(pv, vr[lane + 32], acc1);
                }
            }
        }

        const float inv = 1.0f / l;
        float* orow = O + ((size_t)(b * S_ + i)) * D_ + h * 64;
        orow[lane]      = __uint_as_float(f2tf32(acc0 * inv));
        orow[lane + 32] = __uint_as_float(f2tf32(acc1 * inv));
    }
}

// ---------------- host launcher ----------------
extern "C" void kernel_launch(void* const* d_in, const int* in_sizes, int n_in,
                              void* d_out, int out_size)
{
    (void)in_sizes; (void)n_in; (void)out_size;
    const float* x    = (const float*)d_in[0];
    const int*   mask = (const int*)  d_in[1];
    const float* Wq = (const float*)d_in[2];  const float* bq = (const float*)d_in[3];
    const float* Wk = (const float*)d_in[4];  const float* bk = (const float*)d_in[5];
    const float* Wv = (const float*)d_in[6];  const float* bv = (const float*)d_in[7];
    const float* Wo = (const float*)d_in[8];  const float* bo = (const float*)d_in[9];
    const float* W1 = (const float*)d_in[10]; const float* bf1 = (const float*)d_in[11];
    const float* W2 = (const float*)d_in[12]; const float* bf2 = (const float*)d_in[13];
    const float* g1 = (const float*)d_in[14]; const float* bl1 = (const float*)d_in[15];
    const float* g2 = (const float*)d_in[16]; const float* bl2 = (const float*)d_in[17];
    float* out = (float*)d_out;

    float *n1, *q, *k, *v, *o, *x1, *n2, *ff;
    uint32_t *Wqc, *Wkc, *Wvc, *Woc, *W1c, *W2c;
    cudaGetSymbolAddress((void**)&n1, g_n1);
    cudaGetSymbolAddress((void**)&q,  g_q);
    cudaGetSymbolAddress((void**)&k,  g_k);
    cudaGetSymbolAddress((void**)&v,  g_v);
    cudaGetSymbolAddress((void**)&o,  g_o);
    cudaGetSymbolAddress((void**)&x1, g_x1);
    cudaGetSymbolAddress((void**)&n2, g_n2);
    cudaGetSymbolAddress((void**)&ff, g_ff);
    cudaGetSymbolAddress((void**)&Wqc, g_Wqc);
    cudaGetSymbolAddress((void**)&Wkc, g_Wkc);
    cudaGetSymbolAddress((void**)&Wvc, g_Wvc);
    cudaGetSymbolAddress((void**)&Woc, g_Woc);
    cudaGetSymbolAddress((void**)&W1c, g_W1c);
    cudaGetSymbolAddress((void**)&W2c, g_W2c);

    cudaFuncSetAttribute(attn2_kernel, cudaFuncAttributeMaxDynamicSharedMemorySize, ATTN_SMEM);

    const int M = B_ * S_;  // 4096

    // 0) weight pre-convert to tf32 bits
    cvtw_kernel<<<(D_ * D_) / 1024, 256>>>(Wq, Wqc);
    cvtw_kernel<<<(D_ * D_) / 1024, 256>>>(Wk, Wkc);
    cvtw_kernel<<<(D_ * D_) / 1024, 256>>>(Wv, Wvc);
    cvtw_kernel<<<(D_ * D_) / 1024, 256>>>(Wo, Woc);
    cvtw_kernel<<<(D_ * FF_) / 1024, 256>>>(W1, W1c);
    cvtw_kernel<<<(FF_ * D_) / 1024, 256>>>(W2, W2c);

    // 1) LN1 -> n1 (tf32)
    ln_kernel<<<M, 256>>>(x, g1, bl1, n1);

    // 2) Q, K, V projections (fp32 out)
    {
        dim3 grid(D_ / BN, M / BM);
        mmagemm_kernel<<<grid, 256>>>((const uint32_t*)n1, Wqc, bq, nullptr, q, M, D_, D_, 0, 0);
        mmagemm_kernel<<<grid, 256>>>((const uint32_t*)n1, Wkc, bk, nullptr, k, M, D_, D_, 0, 0);
        mmagemm_kernel<<<grid, 256>>>((const uint32_t*)n1, Wvc, bv, nullptr, v, M, D_, D_, 0, 0);
    }

    // 3) sparse attention -> o (tf32)
    {
        dim3 grid(S_ / QB, H_, B_);
        attn2_kernel<<<grid, 256, ATTN_SMEM>>>(q, k, v, mask, o);
    }

    // 4) output projection + residual -> x1 (fp32)
    {
        dim3 grid(D_ / BN, M / BM);
        mmagemm_kernel<<<grid, 256>>>((const uint32_t*)o, Woc, bo, x, x1, M, D_, D_, 0, 0);
    }

    // 5) LN2 -> n2 (tf32)
    ln_kernel<<<M, 256>>>(x1, g2, bl2, n2);

    // 6) FFN up + GELU -> ff (tf32)
    {
        dim3 grid(FF_ / BN, M / BM);
        mmagemm_kernel<<<grid, 256>>>((const uint32_t*)n2, W1c, bf1, nullptr, ff, M, FF_, D_, 1, 1);
    }

    // 7) FFN down + residual -> out (fp32)
    {
        dim3 grid(D_ / BN, M / BM);
        mmagemm_kernel<<<grid, 256>>>((const uint32_t*)ff, W2c, bf2, x1, out, M, D_, FF_, 0, 0);
    }
}

// round 8
// speedup vs baseline: 1.3737x; 1.1881x over previous
#include <cuda_runtime.h>
#include <math.h>
#include <stdint.h>

#define B_ 2
#define S_ 2048
#define D_ 1024
#define H_ 16
#define DK_ 64
#define FF_ 4096
#define NEG_ (-1000000000.0f)

// ---------------- scratch buffers ----------------
__device__ float g_n1[(size_t)B_ * S_ * D_];    // tf32 bits
__device__ float g_q [(size_t)B_ * S_ * D_];    // fp32
__device__ float g_k [(size_t)B_ * S_ * D_];    // fp32
__device__ float g_v [(size_t)B_ * S_ * D_];    // fp32
__device__ float g_o [(size_t)B_ * S_ * D_];    // tf32 bits
__device__ float g_x1[(size_t)B_ * S_ * D_];    // fp32
__device__ float g_n2[(size_t)B_ * S_ * D_];    // tf32 bits
__device__ float g_ff[(size_t)B_ * S_ * FF_];   // tf32 bits
__device__ uint32_t g_Wqc[(size_t)D_ * D_];
__device__ uint32_t g_Wkc[(size_t)D_ * D_];
__device__ uint32_t g_Wvc[(size_t)D_ * D_];
__device__ uint32_t g_Woc[(size_t)D_ * D_];
__device__ uint32_t g_W1c[(size_t)D_ * FF_];
__device__ uint32_t g_W2c[(size_t)FF_ * D_];

__device__ __forceinline__ uint32_t f2tf32(float f) {
    uint32_t r; asm("cvt.rna.tf32.f32 %0, %1;" : "=r"(r) : "f"(f)); return r;
}

__device__ __forceinline__ void mma_tf32(float c[4], const uint32_t a[4], const uint32_t b[2]) {
    asm volatile(
        "mma.sync.aligned.m16n8k8.row.col.f32.tf32.tf32.f32 "
        "{%0,%1,%2,%3}, {%4,%5,%6,%7}, {%8,%9}, {%0,%1,%2,%3};"
        : "+f"(c[0]), "+f"(c[1]), "+f"(c[2]), "+f"(c[3])
        : "r"(a[0]), "r"(a[1]), "r"(a[2]), "r"(a[3]), "r"(b[0]), "r"(b[1]));
}

// ---------------- weight pre-convert ----------------
__global__ __launch_bounds__(256) void cvtw_kernel(const float* __restrict__ in,
                                                   uint32_t* __restrict__ out)
{
    const int i = (blockIdx.x * 256 + threadIdx.x) * 4;
    const float4 v = *reinterpret_cast<const float4*>(in + i);
    uint4 u;
    u.x = f2tf32(v.x); u.y = f2tf32(v.y); u.z = f2tf32(v.z); u.w = f2tf32(v.w);
    *reinterpret_cast<uint4*>(out + i) = u;
}

// ================= tf32 tensor-core GEMM (single sync per chunk) ==============
#define BM 128
#define BN 128
#define BK 16

__global__ __launch_bounds__(256) void mmagemm_kernel(const uint32_t* __restrict__ A,
                                                      const uint32_t* __restrict__ W,
                                                      const float* __restrict__ bias,
                                                      const float* __restrict__ res,
                                                      float* __restrict__ C,
                                                      int M, int N, int K, int act, int outtf)
{
    __shared__ alignas(128) char Asm[2 * 8192];
    __shared__ alignas(128) char Bsm[2 * 8192];

    const int tid = threadIdx.x;
    const int wid = tid >> 5, lane = tid & 31;
    const int row0 = blockIdx.y * BM;
    const int col0 = blockIdx.x * BN;

    const int m0w = (wid >> 2) * 64;
    const int n0w = (wid & 3) * 32;
    const int g16b = m0w >> 4;
    const int bg8 = n0w >> 3;

    const int ar = tid >> 2;
    const int ac = (tid & 3) << 2;
    const int lga = ar & 7;
    const int swa = (lga >> 1) & 3;
    const int abase = ((ac >> 3) * 8 + (ar >> 4)) * 512 +
                      ((((ac >> 2) & 1) * 2) + ((ar >> 3) & 1)) * 4;
    int aoff[4];
#pragma unroll
    for (int j = 0; j < 4; j++) aoff[j] = abase + (((lga * 4 + j) ^ swa) << 4);

    const int kq = tid >> 6;
    const int nn = tid & 63;
    int boff[2][2];
#pragma unroll
    for (int t = 0; t < 2; t++) {
        const int nv = nn + t * 64;
        const int g8 = nv >> 3;
        const int slot = (((nv & 7) * 4 + kq) ^ (g8 & 3));
#pragma unroll
        for (int kb = 0; kb < 2; kb++)
            boff[t][kb] = ((kb * 16 + g8) << 8) + slot * 8;
    }

    const int aslot = ((lane ^ ((lane >> 3) & 3)) << 4);

    float acc[4][4][4];
#pragma unroll
    for (int mi = 0; mi < 4; mi++)
#pragma unroll
        for (int ni = 0; ni < 4; ni++)
#pragma unroll
            for (int r = 0; r < 4; r++) acc[mi][ni][r] = 0.f;

    const int NC = K / BK;

    // prologue: chunk 0 -> buffer 0
    {
        const uint4 av0 = *reinterpret_cast<const uint4*>(A + (size_t)(row0 + ar) * K + ac);
        const uint4 av1 = *reinterpret_cast<const uint4*>(A + (size_t)(row0 + 64 + ar) * K + ac);
        const uint32_t a0[4] = {av0.x, av0.y, av0.z, av0.w};
        const uint32_t a1[4] = {av1.x, av1.y, av1.z, av1.w};
#pragma unroll
        for (int j = 0; j < 4; j++) {
            *reinterpret_cast<uint32_t*>(Asm + aoff[j]) = a0[j];
            *reinterpret_cast<uint32_t*>(Asm + aoff[j] + 2048) = a1[j];
        }
        uint32_t wreg[2][4];
#pragma unroll
        for (int t = 0; t < 2; t++)
#pragma unroll
            for (int s = 0; s < 4; s++)
                wreg[t][s] = W[(size_t)(kq + s * 4) * N + col0 + nn + t * 64];
#pragma unroll
        for (int t = 0; t < 2; t++)
#pragma unroll
            for (int kb = 0; kb < 2; kb++) {
                uint2 u = {wreg[t][kb * 2 + 0], wreg[t][kb * 2 + 1]};
                *reinterpret_cast<uint2*>(Bsm + boff[t][kb]) = u;
            }
    }
    __syncthreads();

    for (int c = 0; c < NC; c++) {
        const int buf = c & 1;
        const char* Ab = Asm + buf * 8192;
        const char* Bb = Bsm + buf * 8192;

        uint4 av0, av1;
        uint32_t wreg[2][4];
        if (c + 1 < NC) {
            const int k0 = (c + 1) * BK;
            av0 = *reinterpret_cast<const uint4*>(A + (size_t)(row0 + ar) * K + k0 + ac);
            av1 = *reinterpret_cast<const uint4*>(A + (size_t)(row0 + 64 + ar) * K + k0 + ac);
#pragma unroll
            for (int t = 0; t < 2; t++)
#pragma unroll
                for (int s = 0; s < 4; s++)
                    wreg[t][s] = W[(size_t)(k0 + kq + s * 4) * N + col0 + nn + t * 64];
        }

#pragma unroll
        for (int kb = 0; kb < 2; kb++) {
            const char* Abk = Ab + (kb << 12);
            const char* Bbk = Bb + (kb << 12);
            uint4 afr[4];
            uint2 bfr[4];
#pragma unroll
            for (int mi = 0; mi < 4; mi++)
                afr[mi] = *reinterpret_cast<const uint4*>(Abk + ((g16b + mi) << 9) + aslot);
#pragma unroll
            for (int ni = 0; ni < 4; ni++) {
                const int g8 = bg8 + ni;
                bfr[ni] = *reinterpret_cast<const uint2*>(Bbk + (g8 << 8) + ((lane ^ (g8 & 3)) << 3));
            }
#pragma unroll
            for (int mi = 0; mi < 4; mi++)
#pragma unroll
                for (int ni = 0; ni < 4; ni++)
                    mma_tf32(acc[mi][ni],
                             reinterpret_cast<const uint32_t*>(&afr[mi]),
                             reinterpret_cast<const uint32_t*>(&bfr[ni]));
        }

        if (c + 1 < NC) {
            // single-sync double buffer: store(buf^1)@c ordered after readers of
            // buf^1 (iter c-1) by the sync at end of iter c-1.
            char* An = Asm + (buf ^ 1) * 8192;
            char* Bn = Bsm + (buf ^ 1) * 8192;
            const uint32_t a0[4] = {av0.x, av0.y, av0.z, av0.w};
            const uint32_t a1[4] = {av1.x, av1.y, av1.z, av1.w};
#pragma unroll
            for (int j = 0; j < 4; j++) {
                *reinterpret_cast<uint32_t*>(An + aoff[j]) = a0[j];
                *reinterpret_cast<uint32_t*>(An + aoff[j] + 2048) = a1[j];
            }
#pragma unroll
            for (int t = 0; t < 2; t++)
#pragma unroll
                for (int kb = 0; kb < 2; kb++) {
                    uint2 u = {wreg[t][kb * 2 + 0], wreg[t][kb * 2 + 1]};
                    *reinterpret_cast<uint2*>(Bn + boff[t][kb]) = u;
                }
            __syncthreads();
        }
    }

    // epilogue
    const int lg = lane >> 2, lt = lane & 3;
#pragma unroll
    for (int mi = 0; mi < 4; mi++) {
#pragma unroll
        for (int half = 0; half < 2; half++) {
            const int r = row0 + m0w + mi * 16 + lg + half * 8;
#pragma unroll
            for (int ni = 0; ni < 4; ni++) {
                const int cc = col0 + n0w + ni * 8 + lt * 2;
                float2 o;
                o.x = acc[mi][ni][half * 2 + 0] + bias[cc];
                o.y = acc[mi][ni][half * 2 + 1] + bias[cc + 1];
                if (act == 1) {
                    o.x = 0.5f * o.x * (1.0f + erff(o.x * 0.70710678118654752f));
                    o.y = 0.5f * o.y * (1.0f + erff(o.y * 0.70710678118654752f));
                }
                if (res) {
                    const float2 rv = *reinterpret_cast<const float2*>(res + (size_t)r * N + cc);
                    o.x += rv.x; o.y += rv.y;
                }
                if (outtf) {
                    o.x = __uint_as_float(f2tf32(o.x));
                    o.y = __uint_as_float(f2tf32(o.y));
                }
                *reinterpret_cast<float2*>(C + (size_t)r * N + cc) = o;
            }
        }
    }
}

// ---------------- LayerNorm (emits tf32 bits) ----------------
__global__ __launch_bounds__(256) void ln_kernel(const float* __restrict__ x,
                                                 const float* __restrict__ g,
                                                 const float* __restrict__ b,
                                                 float* __restrict__ out)
{
    const int row = blockIdx.x;
    const float* xr = x + (size_t)row * D_;
    float* outr = out + (size_t)row * D_;
    const int tid = threadIdx.x;

    float4 v = reinterpret_cast<const float4*>(xr)[tid];
    float s = v.x + v.y + v.z + v.w;
    float ss = v.x * v.x + v.y * v.y + v.z * v.z + v.w * v.w;

    __shared__ float sh_s[8], sh_ss[8];
    for (int off = 16; off; off >>= 1) {
        s  += __shfl_xor_sync(0xffffffffu, s, off);
        ss += __shfl_xor_sync(0xffffffffu, ss, off);
    }
    const int wid = tid >> 5, lane = tid & 31;
    if (lane == 0) { sh_s[wid] = s; sh_ss[wid] = ss; }
    __syncthreads();
    if (wid == 0) {
        s  = (lane < 8) ? sh_s[lane]  : 0.f;
        ss = (lane < 8) ? sh_ss[lane] : 0.f;
        for (int off = 4; off; off >>= 1) {
            s  += __shfl_xor_sync(0xffffffffu, s, off);
            ss += __shfl_xor_sync(0xffffffffu, ss, off);
        }
        if (lane == 0) { sh_s[0] = s; sh_ss[0] = ss; }
    }
    __syncthreads();
    const float mu = sh_s[0] * (1.0f / D_);
    const float var = sh_ss[0] * (1.0f / D_) - mu * mu;
    const float rstd = rsqrtf(var + 1e-5f);

    float4 gv = reinterpret_cast<const float4*>(g)[tid];
    float4 bv = reinterpret_cast<const float4*>(b)[tid];
    uint4 o;
    o.x = f2tf32((v.x - mu) * rstd * gv.x + bv.x);
    o.y = f2tf32((v.y - mu) * rstd * gv.y + bv.y);
    o.z = f2tf32((v.z - mu) * rstd * gv.z + bv.z);
    o.w = f2tf32((v.w - mu) * rstd * gv.w + bv.w);
    reinterpret_cast<uint4*>(outr)[tid] = o;
}

// ================= sparse attention v3 (fixed empty-segment guard) ===========
#define QB 64
#define KW 192
#define KP 68
#define VP 196
#define ATTN_SMEM ((KW * KP + 64 * VP + 8 * 32) * 4)

__global__ __launch_bounds__(256) void attn3_kernel(const float* __restrict__ Q,
                                                    const float* __restrict__ K,
                                                    const float* __restrict__ V,
                                                    const int* __restrict__ mask,
                                                    float* __restrict__ O)
{
    extern __shared__ float smattn[];
    float* Ks  = smattn;                     // [KW][KP]
    float* Vt  = smattn + KW * KP;           // [64][VP]
    float* psm = smattn + KW * KP + 64 * VP; // [8][32]

    const int qb0 = blockIdx.x * QB;
    const int h = blockIdx.y;
    const int b = blockIdx.z;
    const int tid = threadIdx.x;
    const int warp = tid >> 5, lane = tid & 31;
    const int base_row = qb0 - 128;

    for (int idx = tid; idx < KW * 64; idx += 256) {
        const int r = idx >> 6, d = idx & 63;
        const int j = base_row + r;
        float kv = 0.f, vv = 0.f;
        if (j >= 0) {
            const size_t g = ((size_t)(b * S_ + j)) * D_ + h * 64 + d;
            kv = K[g]; vv = V[g];
        }
        Ks[r * KP + d] = kv;
        Vt[d * VP + r] = vv;
    }
    __syncthreads();

    float* pb = psm + warp * 32;

#pragma unroll 1
    for (int qi = 0; qi < 8; qi++) {
        const int i = qb0 + warp * 8 + qi;
        const int o_in_blk = warp * 8 + qi;
        const float4* q4 = reinterpret_cast<const float4*>(Q + ((size_t)(b * S_ + i)) * D_ + h * 64);
        float4 rq[16];
#pragma unroll
        for (int d = 0; d < 16; d++) rq[d] = __ldg(q4 + d);
        const int* mrow = mask + (size_t)i * S_;

        float m = -INFINITY, l = 0.f, acc0 = 0.f, acc1 = 0.f;

        // ---- strided keys ----
        {
            const int j = i - 256 - 128 * lane;
            float s = -INFINITY;
            if (j >= 0) {
                const float4* kr = reinterpret_cast<const float4*>(K + ((size_t)(b * S_ + j)) * D_ + h * 64);
                float dv = 0.f;
#pragma unroll
                for (int d = 0; d < 16; d++) {
                    const float4 kv = __ldg(kr + d);
                    dv = fmaf(rq[d].x, kv.x, dv);
                    dv = fmaf(rq[d].y, kv.y, dv);
                    dv = fmaf(rq[d].z, kv.z, dv);
                    dv = fmaf(rq[d].w, kv.w, dv);
                }
                s = dv * 0.125f;
                if (mrow[j] == 0) s = NEG_;
            }
            float bm = s;
            for (int off = 16; off; off >>= 1)
                bm = fmaxf(bm, __shfl_xor_sync(0xffffffffu, bm, off));
            if (bm > -1e37f) {
                const float nm = fmaxf(m, bm);
                const float sc = __expf(m - nm);
                const float p = __expf(s - nm);
                float bs = p;
                for (int off = 16; off; off >>= 1)
                    bs += __shfl_xor_sync(0xffffffffu, bs, off);
                l = l * sc + bs;
                acc0 *= sc; acc1 *= sc;
                m = nm;
                const int cnt = (i - 256) / 128 + 1;
                for (int l2 = 0; l2 < cnt; l2++) {
                    const float pv = __shfl_sync(0xffffffffu, p, l2);
                    const int j2 = i - 256 - 128 * l2;
                    const float* vr = V + ((size_t)(b * S_ + j2)) * D_ + h * 64;
                    acc0 = fmaf(pv, __ldg(vr + lane), acc0);
                    acc1 = fmaf(pv, __ldg(vr + lane + 32), acc1);
                }
            }
        }

        // ---- local window: 5 aligned 32-key segments ----
        const int u0 = o_in_blk >> 5;
#pragma unroll 1
        for (int t = 0; t < 5; t++) {
            const int koff = (u0 + t) * 32;
            const int j = base_row + koff + lane;
            float s = -INFINITY;
            if (j >= 0 && j >= i - 128 && j <= i) {
                const float4* kr = reinterpret_cast<const float4*>(Ks + (koff + lane) * KP);
                float dv = 0.f;
#pragma unroll
                for (int d = 0; d < 16; d++) {
                    const float4 kv = kr[d];
                    dv = fmaf(rq[d].x, kv.x, dv);
                    dv = fmaf(rq[d].y, kv.y, dv);
                    dv = fmaf(rq[d].z, kv.z, dv);
                    dv = fmaf(rq[d].w, kv.w, dv);
                }
                s = dv * 0.125f;
                if (mrow[j] == 0) s = NEG_;
            }
            float bm = s;
            for (int off = 16; off; off >>= 1)
                bm = fmaxf(bm, __shfl_xor_sync(0xffffffffu, bm, off));
            if (bm > -1e37f) {   // segment may be entirely out-of-range for boundary queries
                const float nm = fmaxf(m, bm);
                const float sc = __expf(m - nm);
                const float p = __expf(s - nm);
                float bs = p;
                for (int off = 16; off; off >>= 1)
                    bs += __shfl_xor_sync(0xffffffffu, bs, off);
                l = l * sc + bs;
                acc0 *= sc; acc1 *= sc;
                m = nm;

                __syncwarp();
                pb[lane] = p;
                __syncwarp();
                const float4* pv4 = reinterpret_cast<const float4*>(pb);
                const float4* v0 = reinterpret_cast<const float4*>(Vt + lane * VP + koff);
                const float4* v1 = reinterpret_cast<const float4*>(Vt + (lane + 32) * VP + koff);
#pragma unroll
                for (int kk = 0; kk < 8; kk++) {
                    const float4 pp = pv4[kk];
                    const float4 va = v0[kk];
                    const float4 vb = v1[kk];
                    acc0 = fmaf(pp.x, va.x, acc0);
                    acc0 = fmaf(pp.y, va.y, acc0);
                    acc0 = fmaf(pp.z, va.z, acc0);
                    acc0 = fmaf(pp.w, va.w, acc0);
                    acc1 = fmaf(pp.x, vb.x, acc1);
                    acc1 = fmaf(pp.y, vb.y, acc1);
                    acc1 = fmaf(pp.z, vb.z, acc1);
                    acc1 = fmaf(pp.w, vb.w, acc1);
                }
            }
        }

        const float inv = 1.0f / l;
        float* orow = O + ((size_t)(b * S_ + i)) * D_ + h * 64;
        orow[lane]      = __uint_as_float(f2tf32(acc0 * inv));
        orow[lane + 32] = __uint_as_float(f2tf32(acc1 * inv));
    }
}

// ---------------- host launcher ----------------
extern "C" void kernel_launch(void* const* d_in, const int* in_sizes, int n_in,
                              void* d_out, int out_size)
{
    (void)in_sizes; (void)n_in; (void)out_size;
    const float* x    = (const float*)d_in[0];
    const int*   mask = (const int*)  d_in[1];
    const float* Wq = (const float*)d_in[2];  const float* bq = (const float*)d_in[3];
    const float* Wk = (const float*)d_in[4];  const float* bk = (const float*)d_in[5];
    const float* Wv = (const float*)d_in[6];  const float* bv = (const float*)d_in[7];
    const float* Wo = (const float*)d_in[8];  const float* bo = (const float*)d_in[9];
    const float* W1 = (const float*)d_in[10]; const float* bf1 = (const float*)d_in[11];
    const float* W2 = (const float*)d_in[12]; const float* bf2 = (const float*)d_in[13];
    const float* g1 = (const float*)d_in[14]; const float* bl1 = (const float*)d_in[15];
    const float* g2 = (const float*)d_in[16]; const float* bl2 = (const float*)d_in[17];
    float* out = (float*)d_out;

    float *n1, *q, *k, *v, *o, *x1, *n2, *ff;
    uint32_t *Wqc, *Wkc, *Wvc, *Woc, *W1c, *W2c;
    cudaGetSymbolAddress((void**)&n1, g_n1);
    cudaGetSymbolAddress((void**)&q,  g_q);
    cudaGetSymbolAddress((void**)&k,  g_k);
    cudaGetSymbolAddress((void**)&v,  g_v);
    cudaGetSymbolAddress((void**)&o,  g_o);
    cudaGetSymbolAddress((void**)&x1, g_x1);
    cudaGetSymbolAddress((void**)&n2, g_n2);
    cudaGetSymbolAddress((void**)&ff, g_ff);
    cudaGetSymbolAddress((void**)&Wqc, g_Wqc);
    cudaGetSymbolAddress((void**)&Wkc, g_Wkc);
    cudaGetSymbolAddress((void**)&Wvc, g_Wvc);
    cudaGetSymbolAddress((void**)&Woc, g_Woc);
    cudaGetSymbolAddress((void**)&W1c, g_W1c);
    cudaGetSymbolAddress((void**)&W2c, g_W2c);

    cudaFuncSetAttribute(attn3_kernel, cudaFuncAttributeMaxDynamicSharedMemorySize, ATTN_SMEM);

    const int M = B_ * S_;  // 4096

    // 0) weight pre-convert to tf32 bits
    cvtw_kernel<<<(D_ * D_) / 1024, 256>>>(Wq, Wqc);
    cvtw_kernel<<<(D_ * D_) / 1024, 256>>>(Wk, Wkc);
    cvtw_kernel<<<(D_ * D_) / 1024, 256>>>(Wv, Wvc);
    cvtw_kernel<<<(D_ * D_) / 1024, 256>>>(Wo, Woc);
    cvtw_kernel<<<(D_ * FF_) / 1024, 256>>>(W1, W1c);
    cvtw_kernel<<<(FF_ * D_) / 1024, 256>>>(W2, W2c);

    // 1) LN1 -> n1 (tf32)
    ln_kernel<<<M, 256>>>(x, g1, bl1, n1);

    // 2) Q, K, V projections
    {
        dim3 grid(D_ / BN, M / BM);
        mmagemm_kernel<<<grid, 256>>>((const uint32_t*)n1, Wqc, bq, nullptr, q, M, D_, D_, 0, 0);
        mmagemm_kernel<<<grid, 256>>>((const uint32_t*)n1, Wkc, bk, nullptr, k, M, D_, D_, 0, 0);
        mmagemm_kernel<<<grid, 256>>>((const uint32_t*)n1, Wvc, bv, nullptr, v, M, D_, D_, 0, 0);
    }

    // 3) sparse attention -> o (tf32)
    {
        dim3 grid(S_ / QB, H_, B_);
        attn3_kernel<<<grid, 256, ATTN_SMEM>>>(q, k, v, mask, o);
    }

    // 4) output projection + residual -> x1 (fp32)
    {
        dim3 grid(D_ / BN, M / BM);
        mmagemm_kernel<<<grid, 256>>>((const uint32_t*)o, Woc, bo, x, x1, M, D_, D_, 0, 0);
    }

    // 5) LN2 -> n2 (tf32)
    ln_kernel<<<M, 256>>>(x1, g2, bl2, n2);

    // 6) FFN up + GELU -> ff (tf32)
    {
        dim3 grid(FF_ / BN, M / BM);
        mmagemm_kernel<<<grid, 256>>>((const uint32_t*)n2, W1c, bf1, nullptr, ff, M, FF_, D_, 1, 1);
    }

    // 7) FFN down + residual -> out (fp32)
    {
        dim3 grid(D_ / BN, M / BM);
        mmagemm_kernel<<<grid, 256>>>((const uint32_t*)ff, W2c, bf2, x1, out, M, D_, FF_, 0, 0);
    }
}